// round 1
// baseline (speedup 1.0000x reference)
#include <cuda_runtime.h>
#include <cuda_fp16.h>
#include <cstdint>

#define B_ 4
#define N_ 4096
#define F_ 128
#define U_ 64
#define WHX_LD 80   // halves per Whx row: 64 Wh + col64=1.0 + 15 zeros
#define TI 128
#define TJ 128

// ---------------- scratch (device globals; no allocs allowed) ----------------
__device__ float  g_src[B_*N_];
__device__ float  g_dst[B_*N_];
__device__ float  g_maxd[B_];
__device__ float  g_colmean[B_*U_];
__device__ __half g_Whx[(size_t)B_*N_*WHX_LD];

// ---------------- PTX helpers ----------------
__device__ __forceinline__ uint32_t smem_u32(const void* p) {
    return (uint32_t)__cvta_generic_to_shared(p);
}
__device__ __forceinline__ void ldsm_x4(uint32_t a, uint32_t &r0, uint32_t &r1, uint32_t &r2, uint32_t &r3){
    asm volatile("ldmatrix.sync.aligned.m8n8.x4.shared.b16 {%0,%1,%2,%3}, [%4];"
        : "=r"(r0),"=r"(r1),"=r"(r2),"=r"(r3) : "r"(a));
}
__device__ __forceinline__ void ldsm_x4t(uint32_t a, uint32_t &r0, uint32_t &r1, uint32_t &r2, uint32_t &r3){
    asm volatile("ldmatrix.sync.aligned.m8n8.x4.trans.shared.b16 {%0,%1,%2,%3}, [%4];"
        : "=r"(r0),"=r"(r1),"=r"(r2),"=r"(r3) : "r"(a));
}
__device__ __forceinline__ void ldsm_x2t(uint32_t a, uint32_t &r0, uint32_t &r1){
    asm volatile("ldmatrix.sync.aligned.m8n8.x2.trans.shared.b16 {%0,%1}, [%2];"
        : "=r"(r0),"=r"(r1) : "r"(a));
}
__device__ __forceinline__ void mma16816(float* c, uint32_t a0,uint32_t a1,uint32_t a2,uint32_t a3,
                                         uint32_t b0,uint32_t b1){
    asm volatile("mma.sync.aligned.m16n8k16.row.col.f32.f16.f16.f32 "
      "{%0,%1,%2,%3}, {%4,%5,%6,%7}, {%8,%9}, {%0,%1,%2,%3};"
      : "+f"(c[0]),"+f"(c[1]),"+f"(c[2]),"+f"(c[3])
      : "r"(a0),"r"(a1),"r"(a2),"r"(a3),"r"(b0),"r"(b1));
}

// ---------------- k1: Wh = h@W, src/dst, Whx fp16 ----------------
__global__ __launch_bounds__(256) void k1_proj(const float* __restrict__ h,
                                               const float* __restrict__ W,
                                               const float* __restrict__ a) {
    __shared__ float sWm[F_*U_];   // 32 KB
    __shared__ float sH[4*F_];     // 2 KB
    __shared__ float sPart[8], dPart[8];
    const int tid = threadIdx.x;

    {   // stage W
        const float4* Wv = (const float4*)W;
        float4* sWv = (float4*)sWm;
        #pragma unroll
        for (int i = tid; i < F_*U_/4; i += 256) sWv[i] = Wv[i];
    }
    const int u    = tid & 63;
    const int rsub = tid >> 6;       // 0..3 row within pass
    const int wid  = tid >> 5;
    const float a1 = a[u], a2 = a[U_ + u];
    const int row0 = blockIdx.x * 64;

    for (int pass = 0; pass < 16; ++pass) {
        __syncthreads();             // protects sH/sPart reuse (and first-pass W)
        {
            const float* hp = h + (size_t)(row0 + pass*4)*F_;
            #pragma unroll
            for (int i = tid; i < 4*F_; i += 256) sH[i] = hp[i];
        }
        __syncthreads();
        const int row = row0 + pass*4 + rsub;
        float acc = 0.f;
        #pragma unroll
        for (int f = 0; f < F_; ++f)
            acc = fmaf(sH[rsub*F_ + f], sWm[f*U_ + u], acc);

        __half* wp = g_Whx + (size_t)row * WHX_LD;
        wp[u] = __float2half_rn(acc);
        if (u < 16) wp[64 + u] = __float2half((u == 0) ? 1.0f : 0.0f);

        // deterministic reduction of src/dst over u (warp shfl + fixed-order combine)
        float s = acc * a1, d = acc * a2;
        #pragma unroll
        for (int off = 16; off > 0; off >>= 1) {
            s += __shfl_down_sync(0xffffffffu, s, off);
            d += __shfl_down_sync(0xffffffffu, d, off);
        }
        if ((tid & 31) == 0) { sPart[wid] = s; dPart[wid] = d; }
        __syncthreads();
        if (tid < 4) {
            const int r = row0 + pass*4 + tid;
            g_src[r] = sPart[2*tid] + sPart[2*tid+1];
            g_dst[r] = dPart[2*tid] + dPart[2*tid+1];
        }
    }
}

// ---------------- k2: per-batch max(dst) + column mean of Wh (fallback) ----------------
__global__ __launch_bounds__(256) void k2_reduce() {
    const int b = blockIdx.x;
    const int tid = threadIdx.x;
    __shared__ float sred[256];
    float m = -1e30f;
    for (int j = tid; j < N_; j += 256) m = fmaxf(m, g_dst[b*N_ + j]);
    sred[tid] = m; __syncthreads();
    for (int s = 128; s > 0; s >>= 1) {
        if (tid < s) sred[tid] = fmaxf(sred[tid], sred[tid+s]);
        __syncthreads();
    }
    if (tid == 0) g_maxd[b] = sred[0];
    __syncthreads();

    const int u = tid & 63, grp = tid >> 6;
    float sum = 0.f;
    for (int j = grp; j < N_; j += 4)
        sum += __half2float(g_Whx[((size_t)b*N_ + j)*WHX_LD + u]);
    sred[tid] = sum; __syncthreads();
    if (tid < 64)
        g_colmean[b*U_ + tid] = (sred[tid] + sred[tid+64] + sred[tid+128] + sred[tid+192]) * (1.0f/N_);
}

// ---------------- k3: fused masked-softmax attention @ Wh + BN + ReLU ----------------
// smem layout (bytes): sdst[4096]f @0, ssrc[128]f @16384, sM[128]f @16896,
//                      sW half[128][136] @17408 (34816B), sB half[128][88] @52224 (22528B)
#define SMEM_BYTES 74752

__global__ __launch_bounds__(256, 1) void k3_attn(const int* __restrict__ adj,
        const float* __restrict__ gamma, const float* __restrict__ beta,
        const float* __restrict__ mmean, const float* __restrict__ mvar,
        float* __restrict__ out) {
    extern __shared__ char smem[];
    float*  sdst = (float*)smem;
    float*  ssrc = (float*)(smem + 16384);
    float*  sM   = (float*)(smem + 16896);
    __half* sW   = (__half*)(smem + 17408);   // w tile, row stride 136 halves (272B)
    __half* sB   = (__half*)(smem + 52224);   // Whx tile, row stride 88 halves (176B)

    const int tid = threadIdx.x;
    const int b   = blockIdx.y;
    const int i0  = blockIdx.x * TI;
    const float maxd = g_maxd[b];

    {   // stage dst row for this batch
        const float4* dp = (const float4*)(g_dst + b*N_);
        float4* sp = (float4*)sdst;
        #pragma unroll
        for (int i = tid; i < N_/4; i += 256) sp[i] = dp[i];
    }
    if (tid < TI) {
        float s = g_src[b*N_ + i0 + tid];
        ssrc[tid] = s;
        float x = s + maxd;                  // exact row max: leaky monotone
        sM[tid] = fmaxf(x, 0.2f*x);
    }
    __syncthreads();

    const int lane = tid & 31;
    const int wid  = tid >> 5;

    float acc[9][4];
    #pragma unroll
    for (int t = 0; t < 9; ++t) {
        #pragma unroll
        for (int k = 0; k < 4; ++k) acc[t][k] = 0.f;
    }

    // ldmatrix base addresses (per-thread invariant parts)
    const uint32_t a_base = smem_u32(sW) + (uint32_t)(((16*wid + (lane & 15))*136 + (lane >> 4)*8) * 2);
    const uint32_t b_base = smem_u32(sB) + (uint32_t)(((lane & 15)*88 + (lane >> 4)*8) * 2);
    const uint32_t b2base = smem_u32(sB) + (uint32_t)(((lane & 15)*88 + 64) * 2);

    const int c4 = lane;     // column group (4 ints) for w-compute
    const int r8 = wid;      // row subgroup

    for (int jt = 0; jt < N_/TJ; ++jt) {
        const int j0 = jt * TJ;
        // ---- phase 1: compute w tile (coalesced adj int4 loads) ----
        const int4* adjp = (const int4*)(adj + ((size_t)b*N_ + i0)*N_ + j0);
        #pragma unroll 4
        for (int rr = 0; rr < 16; ++rr) {
            const int row = rr*8 + r8;
            const int4 av = adjp[(size_t)row*(N_/4) + c4];
            const float s = ssrc[row], M = sM[row];
            const float4 dv = *(const float4*)(sdst + j0 + c4*4);
            float x0 = s + dv.x, x1 = s + dv.y, x2 = s + dv.z, x3 = s + dv.w;
            x0 = fmaxf(x0, 0.2f*x0); x1 = fmaxf(x1, 0.2f*x1);
            x2 = fmaxf(x2, 0.2f*x2); x3 = fmaxf(x3, 0.2f*x3);
            const float w0 = av.x ? __expf(x0 - M) : 0.f;
            const float w1 = av.y ? __expf(x1 - M) : 0.f;
            const float w2 = av.z ? __expf(x2 - M) : 0.f;
            const float w3 = av.w ? __expf(x3 - M) : 0.f;
            __half2* dst2 = (__half2*)(sW + row*136 + c4*4);
            dst2[0] = __floats2half2_rn(w0, w1);
            dst2[1] = __floats2half2_rn(w2, w3);
        }
        // ---- phase 2: copy Whx tile (fp16) into sB ----
        {
            const uint4* gb = (const uint4*)(g_Whx + ((size_t)b*N_ + j0)*WHX_LD);
            #pragma unroll
            for (int p = 0; p < 5; ++p) {
                const int idx = tid + p*256;        // 1280 uint4 total
                const int row = idx / 10, q = idx % 10;
                *(uint4*)(sB + row*88 + q*8) = gb[idx];
            }
        }
        __syncthreads();
        // ---- phase 3: MMA 128x72 += w(128x128) @ Whx(128x72) ----
        #pragma unroll
        for (int kk = 0; kk < 8; ++kk) {
            uint32_t a0,a1,a2,a3;
            ldsm_x4(a_base + kk*32, a0,a1,a2,a3);
            #pragma unroll
            for (int nt2 = 0; nt2 < 4; ++nt2) {
                uint32_t b0,b1,b2,b3;
                ldsm_x4t(b_base + (uint32_t)(kk*16*176 + nt2*32), b0,b1,b2,b3);
                mma16816(acc[2*nt2],   a0,a1,a2,a3, b0,b1);
                mma16816(acc[2*nt2+1], a0,a1,a2,a3, b2,b3);
            }
            uint32_t e0,e1;
            ldsm_x2t(b2base + (uint32_t)(kk*16*176), e0,e1);
            mma16816(acc[8], a0,a1,a2,a3, e0,e1);
        }
        __syncthreads();
    }

    // ---- epilogue: normalize, BN, ReLU, store ----
    const int q    = lane & 3;
    const int rloc = wid*16 + (lane >> 2);        // rows rloc, rloc+8
    const float dl = __shfl_sync(0xffffffffu, acc[8][0], lane & ~3);
    const float dh = __shfl_sync(0xffffffffu, acc[8][2], lane & ~3);
    const float invl = (dl > 0.f) ? 1.0f/dl : 0.f;
    const float invh = (dh > 0.f) ? 1.0f/dh : 0.f;

    #pragma unroll
    for (int nt = 0; nt < 8; ++nt) {
        const int u0 = nt*8 + 2*q, u1 = u0 + 1;
        const float sc0 = gamma[u0] * rsqrtf(mvar[u0] + 1e-3f);
        const float sc1 = gamma[u1] * rsqrtf(mvar[u1] + 1e-3f);
        const float bi0 = beta[u0] - mmean[u0]*sc0;
        const float bi1 = beta[u1] - mmean[u1]*sc1;

        float v00 = (dl > 0.f) ? acc[nt][0]*invl : g_colmean[b*U_ + u0];
        float v01 = (dl > 0.f) ? acc[nt][1]*invl : g_colmean[b*U_ + u1];
        float v10 = (dh > 0.f) ? acc[nt][2]*invh : g_colmean[b*U_ + u0];
        float v11 = (dh > 0.f) ? acc[nt][3]*invh : g_colmean[b*U_ + u1];

        float2 lo = make_float2(fmaxf(fmaf(v00, sc0, bi0), 0.f), fmaxf(fmaf(v01, sc1, bi1), 0.f));
        float2 hi = make_float2(fmaxf(fmaf(v10, sc0, bi0), 0.f), fmaxf(fmaf(v11, sc1, bi1), 0.f));
        *(float2*)(out + ((size_t)(b*N_ + i0 + rloc    ))*U_ + u0) = lo;
        *(float2*)(out + ((size_t)(b*N_ + i0 + rloc + 8))*U_ + u0) = hi;
    }
}

// ---------------- launch ----------------
extern "C" void kernel_launch(void* const* d_in, const int* in_sizes, int n_in,
                              void* d_out, int out_size) {
    (void)in_sizes; (void)n_in; (void)out_size;
    const float* h     = (const float*)d_in[0];
    const int*   adj   = (const int*)  d_in[1];
    const float* W     = (const float*)d_in[2];
    const float* a     = (const float*)d_in[3];
    const float* gamma = (const float*)d_in[4];
    const float* beta  = (const float*)d_in[5];
    const float* mmean = (const float*)d_in[6];
    const float* mvar  = (const float*)d_in[7];
    float* out = (float*)d_out;

    k1_proj<<<B_*N_/64, 256>>>(h, W, a);
    k2_reduce<<<B_, 256>>>();
    cudaFuncSetAttribute(k3_attn, cudaFuncAttributeMaxDynamicSharedMemorySize, SMEM_BYTES);
    dim3 g3(N_/TI, B_);
    k3_attn<<<g3, 256, SMEM_BYTES>>>(adj, gamma, beta, mmean, mvar, out);
}

// round 2
// speedup vs baseline: 1.2485x; 1.2485x over previous
#include <cuda_runtime.h>
#include <cuda_fp16.h>
#include <cstdint>

#define B_ 4
#define N_ 4096
#define F_ 128
#define U_ 64
#define WHX_LD 80   // halves per Whx row: 64 Wh + col64=1.0 + 15 zeros
#define TI 128
#define TJ 128

// ---------------- scratch (device globals; no allocs allowed) ----------------
__device__ float  g_src[B_*N_];
__device__ float  g_dst[B_*N_];
__device__ float  g_maxd[B_];
__device__ float  g_colmean[B_*U_];
__device__ float  g_cpart[B_*16*U_];
__device__ float  g_mpart[B_*16];
__device__ __half g_Whx[(size_t)B_*N_*WHX_LD];

// ---------------- PTX helpers ----------------
__device__ __forceinline__ uint32_t smem_u32(const void* p) {
    return (uint32_t)__cvta_generic_to_shared(p);
}
__device__ __forceinline__ void ldsm_x4(uint32_t a, uint32_t &r0, uint32_t &r1, uint32_t &r2, uint32_t &r3){
    asm volatile("ldmatrix.sync.aligned.m8n8.x4.shared.b16 {%0,%1,%2,%3}, [%4];"
        : "=r"(r0),"=r"(r1),"=r"(r2),"=r"(r3) : "r"(a));
}
__device__ __forceinline__ void ldsm_x4t(uint32_t a, uint32_t &r0, uint32_t &r1, uint32_t &r2, uint32_t &r3){
    asm volatile("ldmatrix.sync.aligned.m8n8.x4.trans.shared.b16 {%0,%1,%2,%3}, [%4];"
        : "=r"(r0),"=r"(r1),"=r"(r2),"=r"(r3) : "r"(a));
}
__device__ __forceinline__ void ldsm_x2t(uint32_t a, uint32_t &r0, uint32_t &r1){
    asm volatile("ldmatrix.sync.aligned.m8n8.x2.trans.shared.b16 {%0,%1}, [%2];"
        : "=r"(r0),"=r"(r1) : "r"(a));
}
__device__ __forceinline__ void mma16816(float* c, uint32_t a0,uint32_t a1,uint32_t a2,uint32_t a3,
                                         uint32_t b0,uint32_t b1){
    asm volatile("mma.sync.aligned.m16n8k16.row.col.f32.f16.f16.f32 "
      "{%0,%1,%2,%3}, {%4,%5,%6,%7}, {%8,%9}, {%0,%1,%2,%3};"
      : "+f"(c[0]),"+f"(c[1]),"+f"(c[2]),"+f"(c[3])
      : "r"(a0),"r"(a1),"r"(a2),"r"(a3),"r"(b0),"r"(b1));
}
__device__ __forceinline__ void cp_async16(uint32_t smem_addr, const void* gptr){
    asm volatile("cp.async.cg.shared.global [%0], [%1], 16;\n" :: "r"(smem_addr), "l"(gptr));
}
__device__ __forceinline__ void cp_commit(){ asm volatile("cp.async.commit_group;\n"); }
template<int N> __device__ __forceinline__ void cp_wait(){ asm volatile("cp.async.wait_group %0;\n"::"n"(N)); }

// ---------------- k1: Wh = h@W (4x4 register blocking), src/dst, Whx fp16 ----------------
// dyn smem: sW32[128*64] fp32 (32KB) + sHT[128*68] fp32 transposed h tile (34KB)
#define K1_SMEM ((8192 + 128*68) * 4)
__global__ __launch_bounds__(256) void k1_proj(const float* __restrict__ h,
                                               const float* __restrict__ W,
                                               const float* __restrict__ a) {
    extern __shared__ float sm1[];
    float* sW32 = sm1;            // [128][64]
    float* sHT  = sm1 + 8192;     // [128][68] transposed (f major, row minor, pad 68)

    const int tid = threadIdx.x;
    const int r0  = blockIdx.x * 64;

    {   // stage W (fp32)
        const float4* Wv = (const float4*)W;
        float4* sWv = (float4*)sW32;
        #pragma unroll
        for (int i = tid; i < F_*U_/4; i += 256) sWv[i] = Wv[i];
    }
    {   // stage h tile transposed: sHT[f][r] = h[r0+r][f]
        #pragma unroll
        for (int p = 0; p < 8; ++p) {
            const int idx = tid + p*256;          // 2048 float4 chunks
            const int r = idx & 63, c4 = idx >> 6;
            const float4 v = *(const float4*)(h + (size_t)(r0 + r)*F_ + c4*4);
            sHT[(c4*4+0)*68 + r] = v.x;
            sHT[(c4*4+1)*68 + r] = v.y;
            sHT[(c4*4+2)*68 + r] = v.z;
            sHT[(c4*4+3)*68 + r] = v.w;
        }
    }
    __syncthreads();

    const int tx = tid & 15;       // col group: u0 = tx*4
    const int ty = tid >> 4;       // row group: rows ty*4 .. ty*4+3
    const int u0 = tx * 4;

    float acc[4][4];
    #pragma unroll
    for (int i = 0; i < 4; ++i)
        #pragma unroll
        for (int j = 0; j < 4; ++j) acc[i][j] = 0.f;

    #pragma unroll 4
    for (int f = 0; f < F_; ++f) {
        const float4 hv = *(const float4*)(sHT + f*68 + ty*4);
        const float4 wv = *(const float4*)(sW32 + f*64 + u0);
        acc[0][0]=fmaf(hv.x,wv.x,acc[0][0]); acc[0][1]=fmaf(hv.x,wv.y,acc[0][1]);
        acc[0][2]=fmaf(hv.x,wv.z,acc[0][2]); acc[0][3]=fmaf(hv.x,wv.w,acc[0][3]);
        acc[1][0]=fmaf(hv.y,wv.x,acc[1][0]); acc[1][1]=fmaf(hv.y,wv.y,acc[1][1]);
        acc[1][2]=fmaf(hv.y,wv.z,acc[1][2]); acc[1][3]=fmaf(hv.y,wv.w,acc[1][3]);
        acc[2][0]=fmaf(hv.z,wv.x,acc[2][0]); acc[2][1]=fmaf(hv.z,wv.y,acc[2][1]);
        acc[2][2]=fmaf(hv.z,wv.z,acc[2][2]); acc[2][3]=fmaf(hv.z,wv.w,acc[2][3]);
        acc[3][0]=fmaf(hv.w,wv.x,acc[3][0]); acc[3][1]=fmaf(hv.w,wv.y,acc[3][1]);
        acc[3][2]=fmaf(hv.w,wv.z,acc[3][2]); acc[3][3]=fmaf(hv.w,wv.w,acc[3][3]);
    }

    // write Whx (fp16)
    #pragma unroll
    for (int rr = 0; rr < 4; ++rr) {
        const int row = r0 + ty*4 + rr;
        __half2* wp = (__half2*)(g_Whx + (size_t)row*WHX_LD + u0);
        wp[0] = __floats2half2_rn(acc[rr][0], acc[rr][1]);
        wp[1] = __floats2half2_rn(acc[rr][2], acc[rr][3]);
    }
    {   // ones/zeros cols 64..79: 64 rows x 4 half2-pairs per thread-group
        const int r = tid >> 2, q = tid & 3;
        __half2* wp = (__half2*)(g_Whx + (size_t)(r0 + r)*WHX_LD + 64 + q*4);
        wp[0] = (q == 0) ? __floats2half2_rn(1.0f, 0.0f) : __floats2half2_rn(0.0f, 0.0f);
        wp[1] = __floats2half2_rn(0.0f, 0.0f);
    }

    // src/dst: per-row dot with a1/a2, deterministic shfl reduce over 16 lanes
    float a1v[4], a2v[4];
    #pragma unroll
    for (int j = 0; j < 4; ++j) { a1v[j] = a[u0+j]; a2v[j] = a[U_ + u0 + j]; }
    #pragma unroll
    for (int rr = 0; rr < 4; ++rr) {
        float s = fmaf(acc[rr][0],a1v[0], fmaf(acc[rr][1],a1v[1], fmaf(acc[rr][2],a1v[2], acc[rr][3]*a1v[3])));
        float d = fmaf(acc[rr][0],a2v[0], fmaf(acc[rr][1],a2v[1], fmaf(acc[rr][2],a2v[2], acc[rr][3]*a2v[3])));
        #pragma unroll
        for (int off = 8; off > 0; off >>= 1) {
            s += __shfl_down_sync(0xffffffffu, s, off);
            d += __shfl_down_sync(0xffffffffu, d, off);
        }
        if (tx == 0) {
            g_src[r0 + ty*4 + rr] = s;
            g_dst[r0 + ty*4 + rr] = d;
        }
    }
}

// ---------------- k2a: partial max(dst) + partial column sums of Wh ----------------
__global__ __launch_bounds__(256) void k2a_partial() {
    const int b = blockIdx.x, part = blockIdx.y;
    const int tid = threadIdx.x;
    __shared__ float sred[256];

    float m = g_dst[b*N_ + part*256 + tid];
    sred[tid] = m; __syncthreads();
    #pragma unroll
    for (int s = 128; s > 0; s >>= 1) {
        if (tid < s) sred[tid] = fmaxf(sred[tid], sred[tid+s]);
        __syncthreads();
    }
    if (tid == 0) g_mpart[b*16 + part] = sred[0];
    __syncthreads();

    const int u = tid & 63, jg = tid >> 6;
    float sum = 0.f;
    #pragma unroll 8
    for (int j = jg; j < 256; j += 4)
        sum += __half2float(g_Whx[((size_t)b*N_ + part*256 + j)*WHX_LD + u]);
    sred[tid] = sum; __syncthreads();
    if (tid < 64)
        g_cpart[(b*16 + part)*64 + tid] = sred[tid] + sred[tid+64] + sred[tid+128] + sred[tid+192];
}

__global__ void k2b_combine() {
    const int b = blockIdx.x, u = threadIdx.x;   // 64 threads
    float s = 0.f;
    #pragma unroll
    for (int p = 0; p < 16; ++p) s += g_cpart[(b*16 + p)*64 + u];
    g_colmean[b*U_ + u] = s * (1.0f / N_);
    if (u == 0) {
        float m = -1e30f;
        #pragma unroll
        for (int p = 0; p < 16; ++p) m = fmaxf(m, g_mpart[b*16 + p]);
        g_maxd[b] = m;
    }
}

// ---------------- k3: fused masked-softmax attention @ Wh + BN + ReLU (pipelined) ----------------
// smem: sdst f32[4096] @0 (16384B), ssrc[128] @16384, sM[128] @16896,
//       sW0 half[128][136] @17408, sW1 @52224, sB0 half[128][88] @87040, sB1 @109568
#define SMEM_BYTES 132096

__global__ __launch_bounds__(256, 1) void k3_attn(const int* __restrict__ adj,
        const float* __restrict__ gamma, const float* __restrict__ beta,
        const float* __restrict__ mmean, const float* __restrict__ mvar,
        float* __restrict__ out) {
    extern __shared__ char smem[];
    float*  sdst = (float*)smem;
    float*  ssrc = (float*)(smem + 16384);
    float*  sM   = (float*)(smem + 16896);
    __half* sW0  = (__half*)(smem + 17408);
    __half* sW1  = (__half*)(smem + 52224);
    __half* sB0  = (__half*)(smem + 87040);
    __half* sB1  = (__half*)(smem + 109568);

    const int tid = threadIdx.x;
    const int b   = blockIdx.y;
    const int i0  = blockIdx.x * TI;
    const int lane = tid & 31;
    const int wid  = tid >> 5;
    const int c4 = lane;     // column group (4 ints / 4 floats) for w-compute
    const int r8 = wid;      // row subgroup for w-compute

    // ---- async copy of a Whx tile into sBx (one cp.async group) ----
    auto whx_tile = [&](__half* sBx, int jt) {
        const char* gb = (const char*)(g_Whx + ((size_t)b*N_ + jt*TJ)*WHX_LD);
        #pragma unroll
        for (int p = 0; p < 5; ++p) {
            const int idx = tid + p*256;              // 1280 16B chunks
            const int row = idx / 10, q = idx - row*10;
            cp_async16(smem_u32(sBx + row*88 + q*8), gb + (size_t)row*160 + q*16);
        }
        cp_commit();
    };
    // ---- prefetch an adj tile into registers ----
    auto adj_load = [&](int4* av, int jt) {
        const int4* ap = (const int4*)(adj + ((size_t)b*N_ + i0)*N_ + jt*TJ);
        #pragma unroll
        for (int rr = 0; rr < 16; ++rr)
            av[rr] = ap[(size_t)(rr*8 + r8)*(N_/4) + c4];
    };
    // ---- compute w tile from adj registers ----
    auto w_compute = [&](__half* sWx, const int4* av, int jt) {
        const int j0 = jt * TJ;
        const float4 dv = *(const float4*)(sdst + j0 + c4*4);
        #pragma unroll 4
        for (int rr = 0; rr < 16; ++rr) {
            const int row = rr*8 + r8;
            const int4 a4 = av[rr];
            const float s = ssrc[row], M = sM[row];
            float x0 = s + dv.x, x1 = s + dv.y, x2 = s + dv.z, x3 = s + dv.w;
            x0 = fmaxf(x0, 0.2f*x0); x1 = fmaxf(x1, 0.2f*x1);
            x2 = fmaxf(x2, 0.2f*x2); x3 = fmaxf(x3, 0.2f*x3);
            const float w0 = a4.x ? __expf(x0 - M) : 0.f;
            const float w1 = a4.y ? __expf(x1 - M) : 0.f;
            const float w2 = a4.z ? __expf(x2 - M) : 0.f;
            const float w3 = a4.w ? __expf(x3 - M) : 0.f;
            __half2* d2 = (__half2*)(sWx + row*136 + c4*4);
            d2[0] = __floats2half2_rn(w0, w1);
            d2[1] = __floats2half2_rn(w2, w3);
        }
    };

    // ---- stage dst/src/M; meanwhile get tile-0 data moving ----
    whx_tile(sB0, 0);
    int4 av[16];
    adj_load(av, 0);
    {
        const float4* dp = (const float4*)(g_dst + b*N_);
        float4* sp = (float4*)sdst;
        #pragma unroll
        for (int i = tid; i < N_/4; i += 256) sp[i] = dp[i];
    }
    const float maxd = g_maxd[b];
    if (tid < TI) {
        float s = g_src[b*N_ + i0 + tid];
        ssrc[tid] = s;
        float x = s + maxd;                  // exact row max: leaky monotone
        sM[tid] = fmaxf(x, 0.2f*x);
    }
    __syncthreads();

    w_compute(sW0, av, 0);
    whx_tile(sB1, 1);
    adj_load(av, 1);
    cp_wait<1>();            // sB0 landed
    __syncthreads();

    float acc[9][4];
    #pragma unroll
    for (int t = 0; t < 9; ++t)
        #pragma unroll
        for (int k = 0; k < 4; ++k) acc[t][k] = 0.f;

    // ldmatrix per-thread offsets
    const uint32_t off_a  = (uint32_t)(((16*wid + (lane & 15))*136 + (lane >> 4)*8) * 2);
    const uint32_t off_b  = (uint32_t)(((lane & 15)*88 + (lane >> 4)*8) * 2);
    const uint32_t off_b2 = (uint32_t)(((lane & 15)*88 + 64) * 2);
    const uint32_t aW0 = smem_u32(sW0) + off_a, aW1 = smem_u32(sW1) + off_a;
    const uint32_t bB0 = smem_u32(sB0) + off_b, bB1 = smem_u32(sB1) + off_b;
    const uint32_t eB0 = smem_u32(sB0) + off_b2, eB1 = smem_u32(sB1) + off_b2;

    for (int t = 0; t < N_/TJ; ++t) {
        const int c = t & 1;
        const uint32_t abase = c ? aW1 : aW0;
        const uint32_t bbase = c ? bB1 : bB0;
        const uint32_t ebase = c ? eB1 : eB0;
        // ---- MMA 128x72 += w(128x128) @ Whx(128x72) ----
        #pragma unroll
        for (int kk = 0; kk < 8; ++kk) {
            uint32_t a0,a1,a2,a3;
            ldsm_x4(abase + kk*32, a0,a1,a2,a3);
            #pragma unroll
            for (int nt2 = 0; nt2 < 4; ++nt2) {
                uint32_t b0,b1,b2,b3;
                ldsm_x4t(bbase + (uint32_t)(kk*16*176 + nt2*32), b0,b1,b2,b3);
                mma16816(acc[2*nt2],   a0,a1,a2,a3, b0,b1);
                mma16816(acc[2*nt2+1], a0,a1,a2,a3, b2,b3);
            }
            uint32_t e0,e1;
            ldsm_x2t(ebase + (uint32_t)(kk*16*176), e0,e1);
            mma16816(acc[8], a0,a1,a2,a3, e0,e1);
        }
        if (t < 31) {
            w_compute(c ? sW0 : sW1, av, t+1);     // buffer (t+1)&1
            if (t < 30) adj_load(av, t+2);
            cp_wait<0>();                           // sB[(t+1)&1] landed
        }
        __syncthreads();
        if (t < 30) whx_tile(c ? sB1 : sB0, t+2);   // buffer (t+2)&1 == c
    }

    // ---- epilogue: normalize, BN, ReLU, store ----
    const int q    = lane & 3;
    const int rloc = wid*16 + (lane >> 2);        // rows rloc, rloc+8
    const float dl = __shfl_sync(0xffffffffu, acc[8][0], lane & ~3);
    const float dh = __shfl_sync(0xffffffffu, acc[8][2], lane & ~3);
    const float invl = (dl > 0.f) ? 1.0f/dl : 0.f;
    const float invh = (dh > 0.f) ? 1.0f/dh : 0.f;

    #pragma unroll
    for (int nt = 0; nt < 8; ++nt) {
        const int u0 = nt*8 + 2*q, u1 = u0 + 1;
        const float sc0 = gamma[u0] * rsqrtf(mvar[u0] + 1e-3f);
        const float sc1 = gamma[u1] * rsqrtf(mvar[u1] + 1e-3f);
        const float bi0 = beta[u0] - mmean[u0]*sc0;
        const float bi1 = beta[u1] - mmean[u1]*sc1;

        float v00 = (dl > 0.f) ? acc[nt][0]*invl : g_colmean[b*U_ + u0];
        float v01 = (dl > 0.f) ? acc[nt][1]*invl : g_colmean[b*U_ + u1];
        float v10 = (dh > 0.f) ? acc[nt][2]*invh : g_colmean[b*U_ + u0];
        float v11 = (dh > 0.f) ? acc[nt][3]*invh : g_colmean[b*U_ + u1];

        float2 lo = make_float2(fmaxf(fmaf(v00, sc0, bi0), 0.f), fmaxf(fmaf(v01, sc1, bi1), 0.f));
        float2 hi = make_float2(fmaxf(fmaf(v10, sc0, bi0), 0.f), fmaxf(fmaf(v11, sc1, bi1), 0.f));
        *(float2*)(out + ((size_t)(b*N_ + i0 + rloc    ))*U_ + u0) = lo;
        *(float2*)(out + ((size_t)(b*N_ + i0 + rloc + 8))*U_ + u0) = hi;
    }
}

// ---------------- launch ----------------
extern "C" void kernel_launch(void* const* d_in, const int* in_sizes, int n_in,
                              void* d_out, int out_size) {
    (void)in_sizes; (void)n_in; (void)out_size;
    const float* h     = (const float*)d_in[0];
    const int*   adj   = (const int*)  d_in[1];
    const float* W     = (const float*)d_in[2];
    const float* a     = (const float*)d_in[3];
    const float* gamma = (const float*)d_in[4];
    const float* beta  = (const float*)d_in[5];
    const float* mmean = (const float*)d_in[6];
    const float* mvar  = (const float*)d_in[7];
    float* out = (float*)d_out;

    cudaFuncSetAttribute(k1_proj, cudaFuncAttributeMaxDynamicSharedMemorySize, K1_SMEM);
    cudaFuncSetAttribute(k3_attn, cudaFuncAttributeMaxDynamicSharedMemorySize, SMEM_BYTES);

    k1_proj<<<B_*N_/64, 256, K1_SMEM>>>(h, W, a);
    dim3 g2(B_, 16);
    k2a_partial<<<g2, 256>>>();
    k2b_combine<<<B_, 64>>>();
    dim3 g3(N_/TI, B_);
    k3_attn<<<g3, 256, SMEM_BYTES>>>(adj, gamma, beta, mmean, mvar, out);
}

// round 4
// speedup vs baseline: 1.5514x; 1.2426x over previous
#include <cuda_runtime.h>
#include <cuda_fp16.h>
#include <cstdint>

#define B_ 4
#define N_ 4096
#define F_ 128
#define U_ 64
#define WHX_LD 64
#define TI 128
#define TJ 128
#define NT 32          // j-tiles

// ---------------- scratch (device globals; no allocs allowed) ----------------
__device__ float  g_src[B_*N_];
__device__ float  g_dst[B_*N_];
__device__ float  g_maxd[B_];
__device__ float  g_colmean[B_*U_];
__device__ float  g_cpart[B_*16*U_];
__device__ float  g_mpart[B_*16];
__device__ __half g_Whx[(size_t)B_*N_*WHX_LD];

// ---------------- PTX helpers ----------------
__device__ __forceinline__ uint32_t smem_u32(const void* p) {
    return (uint32_t)__cvta_generic_to_shared(p);
}
__device__ __forceinline__ uint32_t h2u(__half2 v){
    return reinterpret_cast<uint32_t&>(v);
}
__device__ __forceinline__ void ldsm_x4t(uint32_t a, uint32_t &r0, uint32_t &r1, uint32_t &r2, uint32_t &r3){
    asm volatile("ldmatrix.sync.aligned.m8n8.x4.trans.shared.b16 {%0,%1,%2,%3}, [%4];"
        : "=r"(r0),"=r"(r1),"=r"(r2),"=r"(r3) : "r"(a));
}
__device__ __forceinline__ void mma16816(float* c, uint32_t a0,uint32_t a1,uint32_t a2,uint32_t a3,
                                         uint32_t b0,uint32_t b1){
    asm volatile("mma.sync.aligned.m16n8k16.row.col.f32.f16.f16.f32 "
      "{%0,%1,%2,%3}, {%4,%5,%6,%7}, {%8,%9}, {%0,%1,%2,%3};"
      : "+f"(c[0]),"+f"(c[1]),"+f"(c[2]),"+f"(c[3])
      : "r"(a0),"r"(a1),"r"(a2),"r"(a3),"r"(b0),"r"(b1));
}
__device__ __forceinline__ void cp_async16(uint32_t smem_addr, const void* gptr){
    asm volatile("cp.async.cg.shared.global [%0], [%1], 16;\n" :: "r"(smem_addr), "l"(gptr));
}
__device__ __forceinline__ void cp_commit(){ asm volatile("cp.async.commit_group;\n"); }
template<int Ng> __device__ __forceinline__ void cp_wait(){ asm volatile("cp.async.wait_group %0;\n"::"n"(Ng)); }

// logical row l (0..15) -> physical sB row, inverse of the A-fragment column perm
__device__ __forceinline__ int rowmap16(int l){
    return ((l >> 2) << 1) | (l & 1) | ((l & 2) << 2);
}

// ---------------- k1: Wh = h@W (4x4 register blocking), src/dst, Whx fp16 ----------------
#define K1_SMEM ((8192 + 128*68) * 4)
__global__ __launch_bounds__(256) void k1_proj(const float* __restrict__ h,
                                               const float* __restrict__ W,
                                               const float* __restrict__ a) {
    extern __shared__ float sm1[];
    float* sW32 = sm1;            // [128][64]
    float* sHT  = sm1 + 8192;     // [128][68]

    const int tid = threadIdx.x;
    const int r0  = blockIdx.x * 64;

    {
        const float4* Wv = (const float4*)W;
        float4* sWv = (float4*)sW32;
        #pragma unroll
        for (int i = tid; i < F_*U_/4; i += 256) sWv[i] = Wv[i];
    }
    {
        #pragma unroll
        for (int p = 0; p < 8; ++p) {
            const int idx = tid + p*256;
            const int r = idx & 63, c4 = idx >> 6;
            const float4 v = *(const float4*)(h + (size_t)(r0 + r)*F_ + c4*4);
            sHT[(c4*4+0)*68 + r] = v.x;
            sHT[(c4*4+1)*68 + r] = v.y;
            sHT[(c4*4+2)*68 + r] = v.z;
            sHT[(c4*4+3)*68 + r] = v.w;
        }
    }
    __syncthreads();

    const int tx = tid & 15;
    const int ty = tid >> 4;
    const int u0 = tx * 4;

    float acc[4][4];
    #pragma unroll
    for (int i = 0; i < 4; ++i)
        #pragma unroll
        for (int j = 0; j < 4; ++j) acc[i][j] = 0.f;

    #pragma unroll 4
    for (int f = 0; f < F_; ++f) {
        const float4 hv = *(const float4*)(sHT + f*68 + ty*4);
        const float4 wv = *(const float4*)(sW32 + f*64 + u0);
        acc[0][0]=fmaf(hv.x,wv.x,acc[0][0]); acc[0][1]=fmaf(hv.x,wv.y,acc[0][1]);
        acc[0][2]=fmaf(hv.x,wv.z,acc[0][2]); acc[0][3]=fmaf(hv.x,wv.w,acc[0][3]);
        acc[1][0]=fmaf(hv.y,wv.x,acc[1][0]); acc[1][1]=fmaf(hv.y,wv.y,acc[1][1]);
        acc[1][2]=fmaf(hv.y,wv.z,acc[1][2]); acc[1][3]=fmaf(hv.y,wv.w,acc[1][3]);
        acc[2][0]=fmaf(hv.z,wv.x,acc[2][0]); acc[2][1]=fmaf(hv.z,wv.y,acc[2][1]);
        acc[2][2]=fmaf(hv.z,wv.z,acc[2][2]); acc[2][3]=fmaf(hv.z,wv.w,acc[2][3]);
        acc[3][0]=fmaf(hv.w,wv.x,acc[3][0]); acc[3][1]=fmaf(hv.w,wv.y,acc[3][1]);
        acc[3][2]=fmaf(hv.w,wv.z,acc[3][2]); acc[3][3]=fmaf(hv.w,wv.w,acc[3][3]);
    }

    #pragma unroll
    for (int rr = 0; rr < 4; ++rr) {
        const int row = r0 + ty*4 + rr;
        __half2* wp = (__half2*)(g_Whx + (size_t)row*WHX_LD + u0);
        wp[0] = __floats2half2_rn(acc[rr][0], acc[rr][1]);
        wp[1] = __floats2half2_rn(acc[rr][2], acc[rr][3]);
    }

    float a1v[4], a2v[4];
    #pragma unroll
    for (int j = 0; j < 4; ++j) { a1v[j] = a[u0+j]; a2v[j] = a[U_ + u0 + j]; }
    #pragma unroll
    for (int rr = 0; rr < 4; ++rr) {
        float s = fmaf(acc[rr][0],a1v[0], fmaf(acc[rr][1],a1v[1], fmaf(acc[rr][2],a1v[2], acc[rr][3]*a1v[3])));
        float d = fmaf(acc[rr][0],a2v[0], fmaf(acc[rr][1],a2v[1], fmaf(acc[rr][2],a2v[2], acc[rr][3]*a2v[3])));
        #pragma unroll
        for (int off = 8; off > 0; off >>= 1) {
            s += __shfl_down_sync(0xffffffffu, s, off);
            d += __shfl_down_sync(0xffffffffu, d, off);
        }
        if (tx == 0) {
            g_src[r0 + ty*4 + rr] = s;
            g_dst[r0 + ty*4 + rr] = d;
        }
    }
}

// ---------------- k2a/k2b: max(dst), column means (fallback path) ----------------
__global__ __launch_bounds__(256) void k2a_partial() {
    const int b = blockIdx.x, part = blockIdx.y;
    const int tid = threadIdx.x;
    __shared__ float sred[256];

    float m = g_dst[b*N_ + part*256 + tid];
    sred[tid] = m; __syncthreads();
    #pragma unroll
    for (int s = 128; s > 0; s >>= 1) {
        if (tid < s) sred[tid] = fmaxf(sred[tid], sred[tid+s]);
        __syncthreads();
    }
    if (tid == 0) g_mpart[b*16 + part] = sred[0];
    __syncthreads();

    const int u = tid & 63, jg = tid >> 6;
    float sum = 0.f;
    #pragma unroll 8
    for (int j = jg; j < 256; j += 4)
        sum += __half2float(g_Whx[((size_t)b*N_ + part*256 + j)*WHX_LD + u]);
    sred[tid] = sum; __syncthreads();
    if (tid < 64)
        g_cpart[(b*16 + part)*64 + tid] = sred[tid] + sred[tid+64] + sred[tid+128] + sred[tid+192];
}

__global__ void k2b_combine() {
    const int b = blockIdx.x, u = threadIdx.x;
    float s = 0.f;
    #pragma unroll
    for (int p = 0; p < 16; ++p) s += g_cpart[(b*16 + p)*64 + u];
    g_colmean[b*U_ + u] = s * (1.0f / N_);
    if (u == 0) {
        float m = -1e30f;
        #pragma unroll
        for (int p = 0; p < 16; ++p) m = fmaxf(m, g_mpart[b*16 + p]);
        g_maxd[b] = m;
    }
}

// ---------------- k3: fully fused, fragment-direct w, triple-buffered Whx ----------------
// smem: sdst f32[4096] @0 (16384B), sB[3] half[128][72] @16384 (+18432 each)
#define SB_STRIDE 72
#define SB_BYTES  (128*SB_STRIDE*2)
#define SMEM_BYTES (16384 + 3*SB_BYTES)

__global__ __launch_bounds__(256, 1) void k3_attn(const int* __restrict__ adj,
        const float* __restrict__ gamma, const float* __restrict__ beta,
        const float* __restrict__ mmean, const float* __restrict__ mvar,
        float* __restrict__ out) {
    extern __shared__ char smem[];
    float*  sdst = (float*)smem;
    __half* sB[3];
    sB[0] = (__half*)(smem + 16384);
    sB[1] = (__half*)(smem + 16384 + SB_BYTES);
    sB[2] = (__half*)(smem + 16384 + 2*SB_BYTES);

    const int tid  = threadIdx.x;
    const int b    = blockIdx.y;
    const int i0   = blockIdx.x * TI;
    const int lane = tid & 31;
    const int wid  = tid >> 5;
    const int q    = lane & 3;
    const int q4   = q * 4;

    // rows owned by this thread's A fragments
    const int r1 = i0 + wid*16 + (lane >> 2);
    const int r2 = r1 + 8;

    // ---- Whx tile cp.async with within-slab row permutation ----
    auto whx_tile = [&](__half* sBx, int jt) {
        const char* gb = (const char*)(g_Whx + ((size_t)b*N_ + jt*TJ)*WHX_LD);
        #pragma unroll
        for (int p = 0; p < 4; ++p) {
            const int idx = tid + p*256;            // 1024 chunks of 16B
            const int row = idx >> 3, qc = idx & 7; // logical row, 16B chunk
            const int prow = (row & 0x70) | rowmap16(row & 15);
            cp_async16(smem_u32(sBx + prow*SB_STRIDE + qc*8), gb + (size_t)row*128 + qc*16);
        }
        cp_commit();
    };

    // ---- prologue: get data moving ----
    whx_tile(sB[0], 0);
    whx_tile(sB[1], 1);

    const int4* ap1 = (const int4*)(adj + ((size_t)b*N_ + r1)*N_);
    const int4* ap2 = (const int4*)(adj + ((size_t)b*N_ + r2)*N_);
    int4 abuf[4][2];
    #pragma unroll
    for (int s = 0; s < 4; ++s) {
        abuf[s][0] = ap1[s*4 + q];
        abuf[s][1] = ap2[s*4 + q];
    }

    {   // stage dst row for this batch (visible after first loop sync)
        const float4* dp = (const float4*)(g_dst + b*N_);
        float4* sp = (float4*)sdst;
        #pragma unroll
        for (int i = tid; i < N_/4; i += 256) sp[i] = dp[i];
    }
    const float maxd = g_maxd[b];
    const float s1 = g_src[b*N_ + r1];
    const float s2 = g_src[b*N_ + r2];
    float x1 = s1 + maxd, x2 = s2 + maxd;
    const float M1 = fmaxf(x1, 0.2f*x1);
    const float M2 = fmaxf(x2, 0.2f*x2);

    float acc[8][4];
    #pragma unroll
    for (int t = 0; t < 8; ++t)
        #pragma unroll
        for (int k = 0; k < 4; ++k) acc[t][k] = 0.f;
    float d1 = 0.f, d2 = 0.f;

    const uint32_t off_b = (uint32_t)(((lane & 15)*SB_STRIDE + (lane >> 4)*8) * 2);
    uint32_t bB[3];
    #pragma unroll
    for (int c = 0; c < 3; ++c) bB[c] = smem_u32(sB[c]) + off_b;

    int c0 = 0, c1 = 1, c2 = 2;
    for (int t = 0; t < NT; ++t) {
        cp_wait<1>();
        __syncthreads();
        if (t < NT-2) whx_tile(sB[c2], t+2); else cp_commit();

        const uint32_t bbase = bB[c0];
        const float* dbase = sdst + t*TJ + q4;

        #pragma unroll
        for (int kk = 0; kk < 8; ++kk) {
            const int slot = kk & 3;
            const float4 dv = *(const float4*)(dbase + kk*16);
            const int4 A1 = abuf[slot][0];
            const int4 A2 = abuf[slot][1];

            float y0 = s1 + dv.x, y1 = s1 + dv.y, y2 = s1 + dv.z, y3 = s1 + dv.w;
            y0 = fmaxf(y0, 0.2f*y0); y1 = fmaxf(y1, 0.2f*y1);
            y2 = fmaxf(y2, 0.2f*y2); y3 = fmaxf(y3, 0.2f*y3);
            const float w00 = A1.x ? __expf(y0 - M1) : 0.f;
            const float w01 = A1.y ? __expf(y1 - M1) : 0.f;
            const float w02 = A1.z ? __expf(y2 - M1) : 0.f;
            const float w03 = A1.w ? __expf(y3 - M1) : 0.f;

            float z0 = s2 + dv.x, z1 = s2 + dv.y, z2 = s2 + dv.z, z3 = s2 + dv.w;
            z0 = fmaxf(z0, 0.2f*z0); z1 = fmaxf(z1, 0.2f*z1);
            z2 = fmaxf(z2, 0.2f*z2); z3 = fmaxf(z3, 0.2f*z3);
            const float w10 = A2.x ? __expf(z0 - M2) : 0.f;
            const float w11 = A2.y ? __expf(z1 - M2) : 0.f;
            const float w12 = A2.z ? __expf(z2 - M2) : 0.f;
            const float w13 = A2.w ? __expf(z3 - M2) : 0.f;

            d1 += (w00 + w01) + (w02 + w03);
            d2 += (w10 + w11) + (w12 + w13);

            const uint32_t a0  = h2u(__floats2half2_rn(w00, w01));
            const uint32_t a2r = h2u(__floats2half2_rn(w02, w03));
            const uint32_t a1  = h2u(__floats2half2_rn(w10, w11));
            const uint32_t a3  = h2u(__floats2half2_rn(w12, w13));

            // prefetch adj 4 slabs ahead
            if (kk < 4) {
                abuf[slot][0] = ap1[t*32 + (kk+4)*4 + q];
                abuf[slot][1] = ap2[t*32 + (kk+4)*4 + q];
            } else if (t < NT-1) {
                abuf[slot][0] = ap1[(t+1)*32 + (kk-4)*4 + q];
                abuf[slot][1] = ap2[(t+1)*32 + (kk-4)*4 + q];
            }

            #pragma unroll
            for (int nt2 = 0; nt2 < 4; ++nt2) {
                uint32_t b0,b1,b2,b3;
                ldsm_x4t(bbase + (uint32_t)(kk*16*SB_STRIDE*2 + nt2*32), b0,b1,b2,b3);
                mma16816(acc[2*nt2],   a0,a1,a2r,a3, b0,b1);
                mma16816(acc[2*nt2+1], a0,a1,a2r,a3, b2,b3);
            }
        }
        const int tmp = c0; c0 = c1; c1 = c2; c2 = tmp;
    }

    // ---- epilogue: normalize, BN, ReLU, store ----
    d1 += __shfl_xor_sync(0xffffffffu, d1, 1);
    d1 += __shfl_xor_sync(0xffffffffu, d1, 2);
    d2 += __shfl_xor_sync(0xffffffffu, d2, 1);
    d2 += __shfl_xor_sync(0xffffffffu, d2, 2);
    const float invl = (d1 > 0.f) ? 1.0f/d1 : 0.f;
    const float invh = (d2 > 0.f) ? 1.0f/d2 : 0.f;

    const int rloc = wid*16 + (lane >> 2);
    #pragma unroll
    for (int nt = 0; nt < 8; ++nt) {
        const int u0 = nt*8 + 2*q, u1 = u0 + 1;
        const float sc0 = gamma[u0] * rsqrtf(mvar[u0] + 1e-3f);
        const float sc1 = gamma[u1] * rsqrtf(mvar[u1] + 1e-3f);
        const float bi0 = beta[u0] - mmean[u0]*sc0;
        const float bi1 = beta[u1] - mmean[u1]*sc1;

        float v00 = (d1 > 0.f) ? acc[nt][0]*invl : g_colmean[b*U_ + u0];
        float v01 = (d1 > 0.f) ? acc[nt][1]*invl : g_colmean[b*U_ + u1];
        float v10 = (d2 > 0.f) ? acc[nt][2]*invh : g_colmean[b*U_ + u0];
        float v11 = (d2 > 0.f) ? acc[nt][3]*invh : g_colmean[b*U_ + u1];

        float2 lo = make_float2(fmaxf(fmaf(v00, sc0, bi0), 0.f), fmaxf(fmaf(v01, sc1, bi1), 0.f));
        float2 hi = make_float2(fmaxf(fmaf(v10, sc0, bi0), 0.f), fmaxf(fmaf(v11, sc1, bi1), 0.f));
        *(float2*)(out + ((size_t)(b*N_ + i0 + rloc    ))*U_ + u0) = lo;
        *(float2*)(out + ((size_t)(b*N_ + i0 + rloc + 8))*U_ + u0) = hi;
    }
}

// ---------------- launch ----------------
extern "C" void kernel_launch(void* const* d_in, const int* in_sizes, int n_in,
                              void* d_out, int out_size) {
    (void)in_sizes; (void)n_in; (void)out_size;
    const float* h     = (const float*)d_in[0];
    const int*   adj   = (const int*)  d_in[1];
    const float* W     = (const float*)d_in[2];
    const float* a     = (const float*)d_in[3];
    const float* gamma = (const float*)d_in[4];
    const float* beta  = (const float*)d_in[5];
    const float* mmean = (const float*)d_in[6];
    const float* mvar  = (const float*)d_in[7];
    float* out = (float*)d_out;

    cudaFuncSetAttribute(k1_proj, cudaFuncAttributeMaxDynamicSharedMemorySize, K1_SMEM);
    cudaFuncSetAttribute(k3_attn, cudaFuncAttributeMaxDynamicSharedMemorySize, SMEM_BYTES);

    k1_proj<<<B_*N_/64, 256, K1_SMEM>>>(h, W, a);
    dim3 g2(B_, 16);
    k2a_partial<<<g2, 256>>>();
    k2b_combine<<<B_, 64>>>();
    dim3 g3(N_/TI, B_);
    k3_attn<<<g3, 256, SMEM_BYTES>>>(adj, gamma, beta, mmean, mvar, out);
}